// round 1
// baseline (speedup 1.0000x reference)
#include <cuda_runtime.h>

#define B_SZ    16384
#define NSTATES 4096
#define GTOT    768
#define NACT    4

// ---------------- packed fp32x2 helpers (sm_103a FFMA2 pipe) ----------------
#define FMA_F32X2(d, a, b, c) \
    asm("fma.rn.f32x2 %0, %1, %2, %3;" : "=l"(d) : "l"(a), "l"(b), "l"(c))
#define DUP_F32X2(d, s) \
    asm("mov.b64 %0, {%1, %1};" : "=l"(d) : "f"(s))

__device__ __forceinline__ float f32x2_lo(unsigned long long v) {
    return __uint_as_float((unsigned)(v & 0xffffffffull));
}
__device__ __forceinline__ float f32x2_hi(unsigned long long v) {
    return __uint_as_float((unsigned)(v >> 32));
}

// ---------------- sort scratch (device globals: no allocation allowed) ------
__device__ int d_count[NACT];
__device__ int d_off[NACT + 1];
__device__ int d_cursor[NACT];
__device__ int d_perm[B_SZ];
// fallback scratch if out buffer only holds logits
__device__ float d_gscratch[(size_t)B_SZ * GTOT];

// ---------------- counting sort over 4 actions ------------------------------
__global__ void k_zero() {
    int t = threadIdx.x;
    if (t < NACT) { d_count[t] = 0; d_cursor[t] = 0; }
}

__global__ void k_hist(const int* __restrict__ act) {
    __shared__ int c[NACT];
    int t = threadIdx.x;
    if (t < NACT) c[t] = 0;
    __syncthreads();
    int i = blockIdx.x * blockDim.x + t;
    if (i < B_SZ) atomicAdd(&c[act[i]], 1);
    __syncthreads();
    if (t < NACT) atomicAdd(&d_count[t], c[t]);
}

__global__ void k_prefix() {
    if (threadIdx.x == 0) {
        int s = 0;
        for (int a = 0; a < NACT; a++) { d_off[a] = s; d_cursor[a] = s; s += d_count[a]; }
        d_off[NACT] = s;
    }
}

__global__ void k_scatter(const int* __restrict__ act) {
    int i = blockIdx.x * blockDim.x + threadIdx.x;
    if (i < B_SZ) {
        int a = act[i];
        int pos = atomicAdd(&d_cursor[a], 1);
        d_perm[pos] = i;
    }
}

// ---------------- transition: per-action GEMM + clip ------------------------
// delta[r, j] = sum_i emb[state_r, moff+i] * D_a[jbase+j, i]
// g_next[b_orig, moff+jbase+j] = clip(g + delta, -1, 1)
// grid: x = m-tiles (64 rows), y = 12 j-tiles over 768, z = action
__global__ void __launch_bounds__(256)
k_transition(const int* __restrict__ csi,
             const float* __restrict__ emb,
             const float* __restrict__ D0, const float* __restrict__ D1,
             const float* __restrict__ D2, const float* __restrict__ D3,
             float* __restrict__ gout)
{
    const int jt = blockIdx.y;
    const int a  = blockIdx.z;
    int jbase, moff, nf; const float* D;
    if (jt < 4)       { jbase = jt * 64;        moff = 0;   nf = 256; D = D0; }
    else if (jt < 8)  { jbase = (jt - 4) * 64;  moff = 256; nf = 256; D = D1; }
    else if (jt < 10) { jbase = (jt - 8) * 64;  moff = 512; nf = 128; D = D2; }
    else              { jbase = (jt - 10) * 64; moff = 640; nf = 128; D = D3; }

    const int row0   = d_off[a] + blockIdx.x * 64;
    const int rowEnd = d_off[a + 1];
    if (row0 >= rowEnd) return;
    const float* __restrict__ Da = D + (size_t)a * nf * nf;

    __shared__ int   permS[64];
    __shared__ int   stateS[64];
    __shared__ float gsm[32][68];
    __shared__ float dsm[32][68];

    const int t = threadIdx.x;
    if (t < 64) {
        int r = row0 + t;
        if (r < rowEnd) { int b = d_perm[r]; permS[t] = b; stateS[t] = csi[b]; }
        else            { permS[t] = -1;     stateS[t] = 0; }
    }
    __syncthreads();

    float acc[4][4] = {};
    const int rs = (t >> 4) * 4;   // 0..60
    const int cs = (t & 15) * 4;   // 0..60

    for (int k0 = 0; k0 < nf; k0 += 32) {
        #pragma unroll
        for (int q = 0; q < 2; q++) {
            int id = t * 2 + q;           // 0..511
            int r  = id >> 3;             // 0..63
            int v  = (id & 7) * 4;        // 0..28
            float4 g4 = *(const float4*)(emb + (size_t)stateS[r] * GTOT + moff + k0 + v);
            gsm[v + 0][r] = g4.x; gsm[v + 1][r] = g4.y;
            gsm[v + 2][r] = g4.z; gsm[v + 3][r] = g4.w;
            float4 dd = *(const float4*)(Da + (size_t)(jbase + r) * nf + k0 + v);
            dsm[v + 0][r] = dd.x; dsm[v + 1][r] = dd.y;
            dsm[v + 2][r] = dd.z; dsm[v + 3][r] = dd.w;
        }
        __syncthreads();
        #pragma unroll
        for (int kk = 0; kk < 32; kk++) {
            float av[4], bv[4];
            #pragma unroll
            for (int i = 0; i < 4; i++) av[i] = gsm[kk][rs + i];
            #pragma unroll
            for (int j = 0; j < 4; j++) bv[j] = dsm[kk][cs + j];
            #pragma unroll
            for (int i = 0; i < 4; i++)
                #pragma unroll
                for (int j = 0; j < 4; j++)
                    acc[i][j] = fmaf(av[i], bv[j], acc[i][j]);
        }
        __syncthreads();
    }

    #pragma unroll
    for (int i = 0; i < 4; i++) {
        int rl = rs + i;
        int borig = permS[rl];
        if (borig < 0) continue;
        int col = moff + jbase + cs;
        float4 g4 = *(const float4*)(emb + (size_t)stateS[rl] * GTOT + col);
        float4 o;
        o.x = fminf(fmaxf(g4.x + acc[i][0], -1.f), 1.f);
        o.y = fminf(fmaxf(g4.y + acc[i][1], -1.f), 1.f);
        o.z = fminf(fmaxf(g4.z + acc[i][2], -1.f), 1.f);
        o.w = fminf(fmaxf(g4.w + acc[i][3], -1.f), 1.f);
        *(float4*)(gout + (size_t)borig * GTOT + col) = o;
    }
}

// ---------------- logits GEMM: C[b,s] = gn[b,:]·W[s,:] + bias[s] ------------
// fp32 with packed f32x2 FMAs. BM=128, BN=128, BK=16, 256 thr, 8x8 micro.
#define GM_BK 16
#define APAD  132

__global__ void __launch_bounds__(256, 2)
k_logits(const float* __restrict__ gn, const float* __restrict__ W,
         const float* __restrict__ bias, float* __restrict__ out)
{
    __shared__ float sA[GM_BK][APAD];
    __shared__ float sB[GM_BK][APAD];

    const int t = threadIdx.x;
    const int mrow0 = blockIdx.y * 128;
    const int ncol0 = blockIdx.x * 128;
    const int tx = t & 15, ty = t >> 4;
    const int rs = ty * 8, cs = tx * 8;

    unsigned long long acc2[8][4];
    #pragma unroll
    for (int i = 0; i < 8; i++)
        #pragma unroll
        for (int j = 0; j < 4; j++) acc2[i][j] = 0ull;

    int lrow[2], lk[2];
    #pragma unroll
    for (int q = 0; q < 2; q++) { int id = t * 2 + q; lrow[q] = id >> 2; lk[q] = (id & 3) * 4; }

    const float* Abase = gn + (size_t)mrow0 * GTOT;
    const float* Bbase = W  + (size_t)ncol0 * GTOT;

    float4 pa[2], pb[2];
    #pragma unroll
    for (int q = 0; q < 2; q++) {
        pa[q] = *(const float4*)(Abase + (size_t)lrow[q] * GTOT + lk[q]);
        pb[q] = *(const float4*)(Bbase + (size_t)lrow[q] * GTOT + lk[q]);
    }

    const int NKT = GTOT / GM_BK;  // 48
    for (int kt = 0; kt < NKT; kt++) {
        #pragma unroll
        for (int q = 0; q < 2; q++) {
            int r = lrow[q], kv = lk[q];
            sA[kv + 0][r] = pa[q].x; sA[kv + 1][r] = pa[q].y;
            sA[kv + 2][r] = pa[q].z; sA[kv + 3][r] = pa[q].w;
            sB[kv + 0][r] = pb[q].x; sB[kv + 1][r] = pb[q].y;
            sB[kv + 2][r] = pb[q].z; sB[kv + 3][r] = pb[q].w;
        }
        __syncthreads();
        if (kt + 1 < NKT) {
            int k0n = (kt + 1) * GM_BK;
            #pragma unroll
            for (int q = 0; q < 2; q++) {
                pa[q] = *(const float4*)(Abase + (size_t)lrow[q] * GTOT + k0n + lk[q]);
                pb[q] = *(const float4*)(Bbase + (size_t)lrow[q] * GTOT + k0n + lk[q]);
            }
        }
        #pragma unroll
        for (int kk = 0; kk < GM_BK; kk++) {
            unsigned long long bp[4];
            const unsigned long long* bp64 = (const unsigned long long*)&sB[kk][cs];
            #pragma unroll
            for (int j = 0; j < 4; j++) bp[j] = bp64[j];
            float av[8];
            #pragma unroll
            for (int i = 0; i < 8; i++) av[i] = sA[kk][rs + i];
            unsigned long long ad[8];
            #pragma unroll
            for (int i = 0; i < 8; i++) DUP_F32X2(ad[i], av[i]);
            #pragma unroll
            for (int i = 0; i < 8; i++)
                #pragma unroll
                for (int j = 0; j < 4; j++)
                    FMA_F32X2(acc2[i][j], ad[i], bp[j], acc2[i][j]);
        }
        __syncthreads();
    }

    float bv[8];
    #pragma unroll
    for (int m = 0; m < 8; m++) bv[m] = bias[ncol0 + cs + m];

    #pragma unroll
    for (int i = 0; i < 8; i++) {
        float c[8];
        #pragma unroll
        for (int j = 0; j < 4; j++) {
            c[2 * j + 0] = f32x2_lo(acc2[i][j]) + bv[2 * j + 0];
            c[2 * j + 1] = f32x2_hi(acc2[i][j]) + bv[2 * j + 1];
        }
        float* orow = out + (size_t)(mrow0 + rs + i) * NSTATES + ncol0 + cs;
        *(float4*)(orow + 0) = make_float4(c[0], c[1], c[2], c[3]);
        *(float4*)(orow + 4) = make_float4(c[4], c[5], c[6], c[7]);
    }
}

// ---------------- launch -----------------------------------------------------
extern "C" void kernel_launch(void* const* d_in, const int* in_sizes, int n_in,
                              void* d_out, int out_size)
{
    const int *csi, *ai;
    const float *emb, *W, *bias, *D0, *D1, *D2, *D3;
    if (in_sizes[4] == NSTATES) {
        // setup_inputs dict order: csi, ai, emb, W_cls, b_cls, D0..D3
        csi = (const int*)d_in[0]; ai = (const int*)d_in[1];
        emb = (const float*)d_in[2]; W = (const float*)d_in[3];
        bias = (const float*)d_in[4];
        D0 = (const float*)d_in[5]; D1 = (const float*)d_in[6];
        D2 = (const float*)d_in[7]; D3 = (const float*)d_in[8];
    } else {
        // reference() signature order: csi, ai, emb, D0..D3, W_cls, b_cls
        csi = (const int*)d_in[0]; ai = (const int*)d_in[1];
        emb = (const float*)d_in[2];
        D0 = (const float*)d_in[3]; D1 = (const float*)d_in[4];
        D2 = (const float*)d_in[5]; D3 = (const float*)d_in[6];
        W = (const float*)d_in[7]; bias = (const float*)d_in[8];
    }

    float* out = (float*)d_out;
    // g_next goes into the output tail if present, else device scratch
    float* gout;
    if ((long long)out_size >= (long long)B_SZ * (NSTATES + GTOT)) {
        gout = out + (size_t)B_SZ * NSTATES;
    } else {
        cudaGetSymbolAddress((void**)&gout, d_gscratch);
    }

    k_zero<<<1, 32>>>();
    k_hist<<<B_SZ / 256, 256>>>(ai);
    k_prefix<<<1, 32>>>();
    k_scatter<<<B_SZ / 256, 256>>>(ai);

    dim3 tg(B_SZ / 64, 12, NACT);
    k_transition<<<tg, 256>>>(csi, emb, D0, D1, D2, D3, gout);

    dim3 gg(NSTATES / 128, B_SZ / 128);
    k_logits<<<gg, 256>>>(gout, W, bias, out);
}

// round 4
// speedup vs baseline: 2.7353x; 2.7353x over previous
#include <cuda_runtime.h>
#include <cuda_fp16.h>
#include <cstdint>

#define B_SZ    16384
#define NSTATES 4096
#define GTOT    768
#define NACT    4
#define K2      1536          // [Ghi | Glo] fp16

// ---------------- packed fp32x2 helpers (sm_103 FFMA2 pipe) -----------------
#define FMA_F32X2(d, a, b, c) \
    asm("fma.rn.f32x2 %0, %1, %2, %3;" : "=l"(d) : "l"(a), "l"(b), "l"(c))
#define DUP_F32X2(d, s) \
    asm("mov.b64 %0, {%1, %1};" : "=l"(d) : "f"(s))
__device__ __forceinline__ float f32x2_lo(unsigned long long v) {
    return __uint_as_float((unsigned)(v & 0xffffffffull));
}
__device__ __forceinline__ float f32x2_hi(unsigned long long v) {
    return __uint_as_float((unsigned)(v >> 32));
}

// ---------------- mma / ldmatrix / cp.async helpers -------------------------
__device__ __forceinline__ uint32_t smem_to_u32(const void* p) {
    uint32_t a;
    asm("{ .reg .u64 t; cvta.to.shared.u64 t, %1; cvt.u32.u64 %0, t; }" : "=r"(a) : "l"(p));
    return a;
}
#define CP_ASYNC16(dst, src) \
    asm volatile("cp.async.cg.shared.global [%0], [%1], 16;" :: "r"(dst), "l"(src))
#define CP_COMMIT() asm volatile("cp.async.commit_group;" ::: "memory")
#define CP_WAIT(n)  asm volatile("cp.async.wait_group %0;" :: "n"(n) : "memory")

#define LDSM_X4(r0, r1, r2, r3, a) \
    asm volatile("ldmatrix.sync.aligned.m8n8.x4.shared.b16 {%0,%1,%2,%3}, [%4];" \
        : "=r"(r0), "=r"(r1), "=r"(r2), "=r"(r3) : "r"(a))

#define MMA16816(d, a, b0v, b1v) \
    asm volatile("mma.sync.aligned.m16n8k16.row.col.f32.f16.f16.f32 " \
        "{%0,%1,%2,%3}, {%4,%5,%6,%7}, {%8,%9}, {%0,%1,%2,%3};" \
        : "+f"((d)[0]), "+f"((d)[1]), "+f"((d)[2]), "+f"((d)[3]) \
        : "r"((a)[0]), "r"((a)[1]), "r"((a)[2]), "r"((a)[3]), "r"(b0v), "r"(b1v))

// ---------------- device scratch --------------------------------------------
__device__ int d_count[NACT];
__device__ int d_off[NACT + 1];
__device__ int d_cursor[NACT];
__device__ int d_perm[B_SZ];
__device__ float d_gscratch[(size_t)B_SZ * GTOT];
__device__ __half d_Ah[(size_t)B_SZ * K2];        // [Ghi | Glo]
__device__ __half d_Wh[(size_t)NSTATES * GTOT];   // W in fp16

// ---------------- counting sort over 4 actions ------------------------------
__global__ void k_zero() {
    int t = threadIdx.x;
    if (t < NACT) { d_count[t] = 0; d_cursor[t] = 0; }
}
__global__ void k_hist(const int* __restrict__ act) {
    __shared__ int c[NACT];
    int t = threadIdx.x;
    if (t < NACT) c[t] = 0;
    __syncthreads();
    int i = blockIdx.x * blockDim.x + t;
    if (i < B_SZ) atomicAdd(&c[act[i]], 1);
    __syncthreads();
    if (t < NACT) atomicAdd(&d_count[t], c[t]);
}
__global__ void k_prefix() {
    if (threadIdx.x == 0) {
        int s = 0;
        for (int a = 0; a < NACT; a++) { d_off[a] = s; d_cursor[a] = s; s += d_count[a]; }
        d_off[NACT] = s;
    }
}
__global__ void k_scatter(const int* __restrict__ act) {
    int i = blockIdx.x * blockDim.x + threadIdx.x;
    if (i < B_SZ) {
        int a = act[i];
        int pos = atomicAdd(&d_cursor[a], 1);
        d_perm[pos] = i;
    }
}

// ---------------- W -> fp16 --------------------------------------------------
__global__ void k_wsplit(const float* __restrict__ W) {
    int i = blockIdx.x * blockDim.x + threadIdx.x;
    float4 w4 = ((const float4*)W)[i];
    ((__half2*)d_Wh)[2 * i]     = __floats2half2_rn(w4.x, w4.y);
    ((__half2*)d_Wh)[2 * i + 1] = __floats2half2_rn(w4.z, w4.w);
}

// ---------------- transition: per-action GEMM + clip + fp16 split -----------
__global__ void __launch_bounds__(256)
k_transition(const int* __restrict__ csi,
             const float* __restrict__ emb,
             const float* __restrict__ D0, const float* __restrict__ D1,
             const float* __restrict__ D2, const float* __restrict__ D3,
             float* __restrict__ gout)
{
    const int jt = blockIdx.y;
    const int a  = blockIdx.z;
    int jbase, moff, nf; const float* D;
    if (jt < 4)       { jbase = jt * 64;        moff = 0;   nf = 256; D = D0; }
    else if (jt < 8)  { jbase = (jt - 4) * 64;  moff = 256; nf = 256; D = D1; }
    else if (jt < 10) { jbase = (jt - 8) * 64;  moff = 512; nf = 128; D = D2; }
    else              { jbase = (jt - 10) * 64; moff = 640; nf = 128; D = D3; }

    const int row0   = d_off[a] + blockIdx.x * 64;
    const int rowEnd = d_off[a + 1];
    if (row0 >= rowEnd) return;
    const float* __restrict__ Da = D + (size_t)a * nf * nf;

    __shared__ int   permS[64];
    __shared__ int   stateS[64];
    __shared__ float gsm[32][68];
    __shared__ float dsm[32][68];

    const int t = threadIdx.x;
    if (t < 64) {
        int r = row0 + t;
        if (r < rowEnd) { int b = d_perm[r]; permS[t] = b; stateS[t] = csi[b]; }
        else            { permS[t] = -1;     stateS[t] = 0; }
    }
    __syncthreads();

    unsigned long long acc2[4][2];
    #pragma unroll
    for (int i = 0; i < 4; i++) { acc2[i][0] = 0ull; acc2[i][1] = 0ull; }
    const int rs = (t >> 4) * 4;
    const int cs = (t & 15) * 4;

    for (int k0 = 0; k0 < nf; k0 += 32) {
        #pragma unroll
        for (int q = 0; q < 2; q++) {
            int id = t * 2 + q;
            int r  = id >> 3;
            int v  = (id & 7) * 4;
            float4 g4 = *(const float4*)(emb + (size_t)stateS[r] * GTOT + moff + k0 + v);
            gsm[v + 0][r] = g4.x; gsm[v + 1][r] = g4.y;
            gsm[v + 2][r] = g4.z; gsm[v + 3][r] = g4.w;
            float4 dd = *(const float4*)(Da + (size_t)(jbase + r) * nf + k0 + v);
            dsm[v + 0][r] = dd.x; dsm[v + 1][r] = dd.y;
            dsm[v + 2][r] = dd.z; dsm[v + 3][r] = dd.w;
        }
        __syncthreads();
        #pragma unroll
        for (int kk = 0; kk < 32; kk++) {
            const unsigned long long* bp = (const unsigned long long*)&dsm[kk][cs];
            unsigned long long b0 = bp[0], b1 = bp[1];
            #pragma unroll
            for (int i = 0; i < 4; i++) {
                unsigned long long ad;
                DUP_F32X2(ad, gsm[kk][rs + i]);
                FMA_F32X2(acc2[i][0], ad, b0, acc2[i][0]);
                FMA_F32X2(acc2[i][1], ad, b1, acc2[i][1]);
            }
        }
        __syncthreads();
    }

    #pragma unroll
    for (int i = 0; i < 4; i++) {
        int rl = rs + i;
        int borig = permS[rl];
        if (borig < 0) continue;
        int col = moff + jbase + cs;
        float4 g4 = *(const float4*)(emb + (size_t)stateS[rl] * GTOT + col);
        float4 o;
        o.x = fminf(fmaxf(g4.x + f32x2_lo(acc2[i][0]), -1.f), 1.f);
        o.y = fminf(fmaxf(g4.y + f32x2_hi(acc2[i][0]), -1.f), 1.f);
        o.z = fminf(fmaxf(g4.z + f32x2_lo(acc2[i][1]), -1.f), 1.f);
        o.w = fminf(fmaxf(g4.w + f32x2_hi(acc2[i][1]), -1.f), 1.f);
        *(float4*)(gout + (size_t)borig * GTOT + col) = o;

        __half2 h0 = __floats2half2_rn(o.x, o.y);
        __half2 h1 = __floats2half2_rn(o.z, o.w);
        float2 f0 = __half22float2(h0);
        float2 f1 = __half22float2(h1);
        __half2 l0 = __floats2half2_rn(o.x - f0.x, o.y - f0.y);
        __half2 l1 = __floats2half2_rn(o.z - f1.x, o.w - f1.y);
        __half2* dh = (__half2*)(d_Ah + (size_t)borig * K2 + col);
        dh[0] = h0; dh[1] = h1;
        __half2* dl = (__half2*)(d_Ah + (size_t)borig * K2 + GTOT + col);
        dl[0] = l0; dl[1] = l1;
    }
}

// ---------------- HMMA logits GEMM ------------------------------------------
// C[b,s] = sum_k Ghi[b,k]*Wh[s,k] + Glo[b,k]*Wh[s,k] + bias[s]
// BM=128, BN=128, BK=64 fp16; 256 thr / 8 warps (4M x 2N), warp tile 32x64.
// 2-stage cp.async double buffer; SW128 xor swizzle for conflict-free ldmatrix.
#define GEMM_ITERS 12                        // 768 / 64
#define STG_B      49152                     // Ahi 16K + Alo 16K + B 16K
#define OFF_ALO    16384
#define OFF_B      32768
#define GSM_TOTAL  (2 * STG_B)               // 96 KB

__device__ __forceinline__ void g_load_stage(int it, int stg, int m0, int n0,
                                             int tid, uint32_t smem_base) {
    const int kc   = it * 64;
    const int row  = tid >> 1;               // 0..127
    const int cb   = (tid & 1) * 4;          // chunk base 0 or 4
    const uint32_t sbase = smem_base + stg * STG_B;
    const __half* ah = d_Ah + (size_t)(m0 + row) * K2 + kc;
    const __half* al = ah + GTOT;
    const __half* bw = d_Wh + (size_t)(n0 + row) * GTOT + kc;
    #pragma unroll
    for (int c = 0; c < 4; c++) {
        int ck = cb + c;                                    // 0..7
        uint32_t sw = row * 128 + ((ck ^ (row & 7)) << 4);  // swizzled byte off
        CP_ASYNC16(sbase + sw,            ah + ck * 8);
        CP_ASYNC16(sbase + OFF_ALO + sw,  al + ck * 8);
        CP_ASYNC16(sbase + OFF_B   + sw,  bw + ck * 8);
    }
}

__global__ void __launch_bounds__(256, 2)
k_logits(const float* __restrict__ bias, float* __restrict__ out)
{
    extern __shared__ char smem[];
    const uint32_t smem_base = smem_to_u32(smem);
    const int tid  = threadIdx.x;
    const int lane = tid & 31;
    const int wid  = tid >> 5;
    const int wm   = wid >> 1;               // 0..3 -> 32 rows each
    const int wn   = wid & 1;                // 0..1 -> 64 cols each
    const int m0 = blockIdx.y * 128;
    const int n0 = blockIdx.x * 128;

    float acc[2][8][4];
    #pragma unroll
    for (int mt = 0; mt < 2; mt++)
        #pragma unroll
        for (int nt = 0; nt < 8; nt++)
            #pragma unroll
            for (int q = 0; q < 4; q++) acc[mt][nt][q] = 0.f;

    // ldmatrix lane addresses (row part fixed per thread)
    const int lr  = lane & 15;               // row within 16-row tile
    const int lk8 = lane >> 4;               // k8 half (0/1)

    g_load_stage(0, 0, m0, n0, tid, smem_base);
    CP_COMMIT();

    for (int it = 0; it < GEMM_ITERS; it++) {
        if (it + 1 < GEMM_ITERS) {
            g_load_stage(it + 1, (it + 1) & 1, m0, n0, tid, smem_base);
            CP_COMMIT();
            CP_WAIT(1);
        } else {
            CP_WAIT(0);
        }
        __syncthreads();

        const uint32_t sbase = smem_base + (it & 1) * STG_B;
        #pragma unroll
        for (int ks = 0; ks < 4; ks++) {
            const int k8 = ks * 2 + lk8;     // 0..7
            uint32_t ahi[2][4], alo[2][4], bfr[4][4];
            #pragma unroll
            for (int mt = 0; mt < 2; mt++) {
                int row = wm * 32 + mt * 16 + lr;
                uint32_t ad = sbase + row * 128 + ((k8 ^ (row & 7)) << 4);
                LDSM_X4(ahi[mt][0], ahi[mt][1], ahi[mt][2], ahi[mt][3], ad);
                LDSM_X4(alo[mt][0], alo[mt][1], alo[mt][2], alo[mt][3], ad + OFF_ALO);
            }
            #pragma unroll
            for (int np = 0; np < 4; np++) {
                int rn = wn * 64 + np * 16 + lr;
                uint32_t bd = sbase + OFF_B + rn * 128 + ((k8 ^ (rn & 7)) << 4);
                LDSM_X4(bfr[np][0], bfr[np][1], bfr[np][2], bfr[np][3], bd);
            }
            #pragma unroll
            for (int mt = 0; mt < 2; mt++)
                #pragma unroll
                for (int np = 0; np < 4; np++) {
                    MMA16816(acc[mt][2 * np],     ahi[mt], bfr[np][0], bfr[np][2]);
                    MMA16816(acc[mt][2 * np + 1], ahi[mt], bfr[np][1], bfr[np][3]);
                    MMA16816(acc[mt][2 * np],     alo[mt], bfr[np][0], bfr[np][2]);
                    MMA16816(acc[mt][2 * np + 1], alo[mt], bfr[np][1], bfr[np][3]);
                }
        }
        __syncthreads();
    }

    // epilogue: float2 stores (full 32B sectors), bias added
    const int cq = 2 * (lane & 3);
    float2 bv[8];
    #pragma unroll
    for (int nt = 0; nt < 8; nt++)
        bv[nt] = *(const float2*)(bias + n0 + wn * 64 + nt * 8 + cq);

    #pragma unroll
    for (int mt = 0; mt < 2; mt++) {
        int rg = m0 + wm * 32 + mt * 16 + (lane >> 2);
        #pragma unroll
        for (int nt = 0; nt < 8; nt++) {
            float* p = out + (size_t)rg * NSTATES + n0 + wn * 64 + nt * 8 + cq;
            float2 v0 = make_float2(acc[mt][nt][0] + bv[nt].x, acc[mt][nt][1] + bv[nt].y);
            float2 v1 = make_float2(acc[mt][nt][2] + bv[nt].x, acc[mt][nt][3] + bv[nt].y);
            *(float2*)p = v0;
            *(float2*)(p + (size_t)8 * NSTATES) = v1;
        }
    }
}

// ---------------- launch -----------------------------------------------------
extern "C" void kernel_launch(void* const* d_in, const int* in_sizes, int n_in,
                              void* d_out, int out_size)
{
    const int *csi, *ai;
    const float *emb, *W, *bias, *D0, *D1, *D2, *D3;
    if (in_sizes[4] == NSTATES) {
        csi = (const int*)d_in[0]; ai = (const int*)d_in[1];
        emb = (const float*)d_in[2]; W = (const float*)d_in[3];
        bias = (const float*)d_in[4];
        D0 = (const float*)d_in[5]; D1 = (const float*)d_in[6];
        D2 = (const float*)d_in[7]; D3 = (const float*)d_in[8];
    } else {
        csi = (const int*)d_in[0]; ai = (const int*)d_in[1];
        emb = (const float*)d_in[2];
        D0 = (const float*)d_in[3]; D1 = (const float*)d_in[4];
        D2 = (const float*)d_in[5]; D3 = (const float*)d_in[6];
        W = (const float*)d_in[7]; bias = (const float*)d_in[8];
    }

    float* out = (float*)d_out;
    float* gout;
    if ((long long)out_size >= (long long)B_SZ * (NSTATES + GTOT)) {
        gout = out + (size_t)B_SZ * NSTATES;
    } else {
        cudaGetSymbolAddress((void**)&gout, d_gscratch);
    }

    k_zero<<<1, 32>>>();
    k_hist<<<B_SZ / 256, 256>>>(ai);
    k_prefix<<<1, 32>>>();
    k_scatter<<<B_SZ / 256, 256>>>(ai);

    k_wsplit<<<(NSTATES * GTOT / 4) / 256, 256>>>(W);

    dim3 tg(B_SZ / 64, 12, NACT);
    k_transition<<<tg, 256>>>(csi, emb, D0, D1, D2, D3, gout);

    cudaFuncSetAttribute(k_logits, cudaFuncAttributeMaxDynamicSharedMemorySize, GSM_TOTAL);
    dim3 gg(NSTATES / 128, B_SZ / 128);
    k_logits<<<gg, 256, GSM_TOTAL>>>(bias, out);
}

// round 6
// speedup vs baseline: 3.1101x; 1.1370x over previous
#include <cuda_runtime.h>
#include <cuda_fp16.h>
#include <cstdint>

#define B_SZ    16384
#define NSTATES 4096
#define GTOT    768
#define NACT    4

// ---------------- packed fp32x2 helpers (sm_103 FFMA2 pipe) -----------------
#define FMA_F32X2(d, a, b, c) \
    asm("fma.rn.f32x2 %0, %1, %2, %3;" : "=l"(d) : "l"(a), "l"(b), "l"(c))
#define DUP_F32X2(d, s) \
    asm("mov.b64 %0, {%1, %1};" : "=l"(d) : "f"(s))
__device__ __forceinline__ float f32x2_lo(unsigned long long v) {
    return __uint_as_float((unsigned)(v & 0xffffffffull));
}
__device__ __forceinline__ float f32x2_hi(unsigned long long v) {
    return __uint_as_float((unsigned)(v >> 32));
}

// ---------------- mma / ldmatrix / cp.async helpers -------------------------
__device__ __forceinline__ uint32_t smem_to_u32(const void* p) {
    uint32_t a;
    asm("{ .reg .u64 t; cvta.to.shared.u64 t, %1; cvt.u32.u64 %0, t; }" : "=r"(a) : "l"(p));
    return a;
}
#define CP_ASYNC16(dst, src) \
    asm volatile("cp.async.cg.shared.global [%0], [%1], 16;" :: "r"(dst), "l"(src))
#define CP_COMMIT() asm volatile("cp.async.commit_group;" ::: "memory")
#define CP_WAIT(n)  asm volatile("cp.async.wait_group %0;" :: "n"(n) : "memory")

#define LDSM_X4(r0, r1, r2, r3, a) \
    asm volatile("ldmatrix.sync.aligned.m8n8.x4.shared.b16 {%0,%1,%2,%3}, [%4];" \
        : "=r"(r0), "=r"(r1), "=r"(r2), "=r"(r3) : "r"(a))

#define MMA16816(d, a, b0v, b1v) \
    asm volatile("mma.sync.aligned.m16n8k16.row.col.f32.f16.f16.f32 " \
        "{%0,%1,%2,%3}, {%4,%5,%6,%7}, {%8,%9}, {%0,%1,%2,%3};" \
        : "+f"((d)[0]), "+f"((d)[1]), "+f"((d)[2]), "+f"((d)[3]) \
        : "r"((a)[0]), "r"((a)[1]), "r"((a)[2]), "r"((a)[3]), "r"(b0v), "r"(b1v))

// ---------------- device scratch --------------------------------------------
__device__ int d_off[NACT + 1];
__device__ int d_cursor[NACT];
__device__ int d_perm[B_SZ];
__device__ float d_gscratch[(size_t)B_SZ * GTOT];
__device__ __half d_Ah[(size_t)B_SZ * GTOT];      // g_next in fp16
__device__ __half d_Wh[(size_t)NSTATES * GTOT];   // W in fp16

// ---------------- fused zero + hist + prefix (1 block) ----------------------
__global__ void k_sortinit(const int* __restrict__ act) {
    __shared__ int c[NACT];
    int t = threadIdx.x;
    if (t < NACT) c[t] = 0;
    __syncthreads();
    for (int i = t; i < B_SZ; i += blockDim.x) atomicAdd(&c[act[i]], 1);
    __syncthreads();
    if (t == 0) {
        int s = 0;
        for (int a = 0; a < NACT; a++) { d_off[a] = s; d_cursor[a] = s; s += c[a]; }
        d_off[NACT] = s;
    }
}
__global__ void k_scatter(const int* __restrict__ act) {
    int i = blockIdx.x * blockDim.x + threadIdx.x;
    if (i < B_SZ) {
        int a = act[i];
        int pos = atomicAdd(&d_cursor[a], 1);
        d_perm[pos] = i;
    }
}

// ---------------- W -> fp16 --------------------------------------------------
__global__ void k_wsplit(const float* __restrict__ W) {
    int i = blockIdx.x * blockDim.x + threadIdx.x;
    float4 w4 = ((const float4*)W)[i];
    ((__half2*)d_Wh)[2 * i]     = __floats2half2_rn(w4.x, w4.y);
    ((__half2*)d_Wh)[2 * i + 1] = __floats2half2_rn(w4.z, w4.w);
}

// ---------------- transition: per-action GEMM + clip + fp16 cast ------------
__global__ void __launch_bounds__(256)
k_transition(const int* __restrict__ csi,
             const float* __restrict__ emb,
             const float* __restrict__ D0, const float* __restrict__ D1,
             const float* __restrict__ D2, const float* __restrict__ D3,
             float* __restrict__ gout)
{
    const int jt = blockIdx.y;
    const int a  = blockIdx.z;
    int jbase, moff, nf; const float* D;
    if (jt < 4)       { jbase = jt * 64;        moff = 0;   nf = 256; D = D0; }
    else if (jt < 8)  { jbase = (jt - 4) * 64;  moff = 256; nf = 256; D = D1; }
    else if (jt < 10) { jbase = (jt - 8) * 64;  moff = 512; nf = 128; D = D2; }
    else              { jbase = (jt - 10) * 64; moff = 640; nf = 128; D = D3; }

    const int row0   = d_off[a] + blockIdx.x * 64;
    const int rowEnd = d_off[a + 1];
    if (row0 >= rowEnd) return;
    const float* __restrict__ Da = D + (size_t)a * nf * nf;

    __shared__ int   permS[64];
    __shared__ int   stateS[64];
    __shared__ float gsm[32][68];
    __shared__ float dsm[32][68];

    const int t = threadIdx.x;
    if (t < 64) {
        int r = row0 + t;
        if (r < rowEnd) { int b = d_perm[r]; permS[t] = b; stateS[t] = csi[b]; }
        else            { permS[t] = -1;     stateS[t] = 0; }
    }
    __syncthreads();

    unsigned long long acc2[4][2];
    #pragma unroll
    for (int i = 0; i < 4; i++) { acc2[i][0] = 0ull; acc2[i][1] = 0ull; }
    const int rs = (t >> 4) * 4;
    const int cs = (t & 15) * 4;

    for (int k0 = 0; k0 < nf; k0 += 32) {
        #pragma unroll
        for (int q = 0; q < 2; q++) {
            int id = t * 2 + q;
            int r  = id >> 3;
            int v  = (id & 7) * 4;
            float4 g4 = *(const float4*)(emb + (size_t)stateS[r] * GTOT + moff + k0 + v);
            gsm[v + 0][r] = g4.x; gsm[v + 1][r] = g4.y;
            gsm[v + 2][r] = g4.z; gsm[v + 3][r] = g4.w;
            float4 dd = *(const float4*)(Da + (size_t)(jbase + r) * nf + k0 + v);
            dsm[v + 0][r] = dd.x; dsm[v + 1][r] = dd.y;
            dsm[v + 2][r] = dd.z; dsm[v + 3][r] = dd.w;
        }
        __syncthreads();
        #pragma unroll
        for (int kk = 0; kk < 32; kk++) {
            const unsigned long long* bp = (const unsigned long long*)&dsm[kk][cs];
            unsigned long long b0 = bp[0], b1 = bp[1];
            #pragma unroll
            for (int i = 0; i < 4; i++) {
                unsigned long long ad;
                DUP_F32X2(ad, gsm[kk][rs + i]);
                FMA_F32X2(acc2[i][0], ad, b0, acc2[i][0]);
                FMA_F32X2(acc2[i][1], ad, b1, acc2[i][1]);
            }
        }
        __syncthreads();
    }

    #pragma unroll
    for (int i = 0; i < 4; i++) {
        int rl = rs + i;
        int borig = permS[rl];
        if (borig < 0) continue;
        int col = moff + jbase + cs;
        float4 g4 = *(const float4*)(emb + (size_t)stateS[rl] * GTOT + col);
        float4 o;
        o.x = fminf(fmaxf(g4.x + f32x2_lo(acc2[i][0]), -1.f), 1.f);
        o.y = fminf(fmaxf(g4.y + f32x2_hi(acc2[i][0]), -1.f), 1.f);
        o.z = fminf(fmaxf(g4.z + f32x2_lo(acc2[i][1]), -1.f), 1.f);
        o.w = fminf(fmaxf(g4.w + f32x2_hi(acc2[i][1]), -1.f), 1.f);
        *(float4*)(gout + (size_t)borig * GTOT + col) = o;

        __half2* dh = (__half2*)(d_Ah + (size_t)borig * GTOT + col);
        dh[0] = __floats2half2_rn(o.x, o.y);
        dh[1] = __floats2half2_rn(o.z, o.w);
    }
}

// ---------------- HMMA logits GEMM ------------------------------------------
// C[b,s] = sum_k A[b,k]*Wh[s,k] + bias[s]      (A, W fp16; f32 accum)
// BM=128, BN=128, BK=64; 256 thr / 8 warps (4M x 2N), warp tile 32x64.
// 2-stage cp.async double buffer; xor swizzle for conflict-free ldmatrix.
#define GEMM_ITERS 12                        // 768 / 64
#define STG_B      32768                     // A 16K + B 16K
#define OFF_B      16384
#define GSM_TOTAL  (2 * STG_B)               // 64 KB

__device__ __forceinline__ void g_load_stage(int it, int stg, int m0, int n0,
                                             int tid, uint32_t smem_base) {
    const int kc   = it * 64;
    const int row  = tid >> 1;               // 0..127
    const int cb   = (tid & 1) * 4;          // chunk base 0 or 4
    const uint32_t sbase = smem_base + stg * STG_B;
    const __half* ah = d_Ah + (size_t)(m0 + row) * GTOT + kc;
    const __half* bw = d_Wh + (size_t)(n0 + row) * GTOT + kc;
    #pragma unroll
    for (int c = 0; c < 4; c++) {
        int ck = cb + c;                                    // 0..7
        uint32_t sw = row * 128 + ((ck ^ (row & 7)) << 4);  // swizzled byte off
        CP_ASYNC16(sbase + sw,           ah + ck * 8);
        CP_ASYNC16(sbase + OFF_B + sw,   bw + ck * 8);
    }
}

__global__ void __launch_bounds__(256, 3)
k_logits(const float* __restrict__ bias, float* __restrict__ out)
{
    extern __shared__ char smem[];
    const uint32_t smem_base = smem_to_u32(smem);
    const int tid  = threadIdx.x;
    const int lane = tid & 31;
    const int wid  = tid >> 5;
    const int wm   = wid >> 1;               // 0..3 -> 32 rows each
    const int wn   = wid & 1;                // 0..1 -> 64 cols each
    const int m0 = blockIdx.y * 128;
    const int n0 = blockIdx.x * 128;

    float acc[2][8][4];
    #pragma unroll
    for (int mt = 0; mt < 2; mt++)
        #pragma unroll
        for (int nt = 0; nt < 8; nt++)
            #pragma unroll
            for (int q = 0; q < 4; q++) acc[mt][nt][q] = 0.f;

    const int lr  = lane & 15;               // row within 16-row tile
    const int lk8 = lane >> 4;               // k8 half (0/1)

    g_load_stage(0, 0, m0, n0, tid, smem_base);
    CP_COMMIT();

    for (int it = 0; it < GEMM_ITERS; it++) {
        if (it + 1 < GEMM_ITERS) {
            g_load_stage(it + 1, (it + 1) & 1, m0, n0, tid, smem_base);
            CP_COMMIT();
            CP_WAIT(1);
        } else {
            CP_WAIT(0);
        }
        __syncthreads();

        const uint32_t sbase = smem_base + (it & 1) * STG_B;
        #pragma unroll
        for (int ks = 0; ks < 4; ks++) {
            const int k8 = ks * 2 + lk8;     // 0..7
            uint32_t afr[2][4], bfr[4][4];
            #pragma unroll
            for (int mt = 0; mt < 2; mt++) {
                int row = wm * 32 + mt * 16 + lr;
                uint32_t ad = sbase + row * 128 + ((k8 ^ (row & 7)) << 4);
                LDSM_X4(afr[mt][0], afr[mt][1], afr[mt][2], afr[mt][3], ad);
            }
            #pragma unroll
            for (int np = 0; np < 4; np++) {
                int rn = wn * 64 + np * 16 + lr;
                uint32_t bd = sbase + OFF_B + rn * 128 + ((k8 ^ (rn & 7)) << 4);
                LDSM_X4(bfr[np][0], bfr[np][1], bfr[np][2], bfr[np][3], bd);
            }
            #pragma unroll
            for (int mt = 0; mt < 2; mt++)
                #pragma unroll
                for (int np = 0; np < 4; np++) {
                    MMA16816(acc[mt][2 * np],     afr[mt], bfr[np][0], bfr[np][2]);
                    MMA16816(acc[mt][2 * np + 1], afr[mt], bfr[np][1], bfr[np][3]);
                }
        }
        __syncthreads();
    }

    // epilogue: float2 stores (32B sectors), bias added
    const int cq = 2 * (lane & 3);
    float2 bv[8];
    #pragma unroll
    for (int nt = 0; nt < 8; nt++)
        bv[nt] = *(const float2*)(bias + n0 + wn * 64 + nt * 8 + cq);

    #pragma unroll
    for (int mt = 0; mt < 2; mt++) {
        int rg = m0 + wm * 32 + mt * 16 + (lane >> 2);
        #pragma unroll
        for (int nt = 0; nt < 8; nt++) {
            float* p = out + (size_t)rg * NSTATES + n0 + wn * 64 + nt * 8 + cq;
            float2 v0 = make_float2(acc[mt][nt][0] + bv[nt].x, acc[mt][nt][1] + bv[nt].y);
            float2 v1 = make_float2(acc[mt][nt][2] + bv[nt].x, acc[mt][nt][3] + bv[nt].y);
            *(float2*)p = v0;
            *(float2*)(p + (size_t)8 * NSTATES) = v1;
        }
    }
}

// ---------------- launch -----------------------------------------------------
extern "C" void kernel_launch(void* const* d_in, const int* in_sizes, int n_in,
                              void* d_out, int out_size)
{
    const int *csi, *ai;
    const float *emb, *W, *bias, *D0, *D1, *D2, *D3;
    if (in_sizes[4] == NSTATES) {
        csi = (const int*)d_in[0]; ai = (const int*)d_in[1];
        emb = (const float*)d_in[2]; W = (const float*)d_in[3];
        bias = (const float*)d_in[4];
        D0 = (const float*)d_in[5]; D1 = (const float*)d_in[6];
        D2 = (const float*)d_in[7]; D3 = (const float*)d_in[8];
    } else {
        csi = (const int*)d_in[0]; ai = (const int*)d_in[1];
        emb = (const float*)d_in[2];
        D0 = (const float*)d_in[3]; D1 = (const float*)d_in[4];
        D2 = (const float*)d_in[5]; D3 = (const float*)d_in[6];
        W = (const float*)d_in[7]; bias = (const float*)d_in[8];
    }

    float* out = (float*)d_out;
    float* gout;
    if ((long long)out_size >= (long long)B_SZ * (NSTATES + GTOT)) {
        gout = out + (size_t)B_SZ * NSTATES;
    } else {
        cudaGetSymbolAddress((void**)&gout, d_gscratch);
    }

    k_sortinit<<<1, 1024>>>(ai);
    k_scatter<<<B_SZ / 256, 256>>>(ai);

    k_wsplit<<<(NSTATES * GTOT / 4) / 256, 256>>>(W);

    dim3 tg(B_SZ / 64, 12, NACT);
    k_transition<<<tg, 256>>>(csi, emb, D0, D1, D2, D3, gout);

    cudaFuncSetAttribute(k_logits, cudaFuncAttributeMaxDynamicSharedMemorySize, GSM_TOTAL);
    dim3 gg(NSTATES / 128, B_SZ / 128);
    k_logits<<<gg, 256, GSM_TOTAL>>>(bias, out);
}

// round 8
// speedup vs baseline: 4.3258x; 1.3909x over previous
#include <cuda_runtime.h>
#include <cuda_fp16.h>
#include <cstdint>

#define B_SZ    16384
#define NSTATES 4096
#define GTOT    768
#define NACT    4

// ---------------- packed fp32x2 helpers (sm_103 FFMA2 pipe) -----------------
#define FMA_F32X2(d, a, b, c) \
    asm("fma.rn.f32x2 %0, %1, %2, %3;" : "=l"(d) : "l"(a), "l"(b), "l"(c))
#define DUP_F32X2(d, s) \
    asm("mov.b64 %0, {%1, %1};" : "=l"(d) : "f"(s))
__device__ __forceinline__ float f32x2_lo(unsigned long long v) {
    return __uint_as_float((unsigned)(v & 0xffffffffull));
}
__device__ __forceinline__ float f32x2_hi(unsigned long long v) {
    return __uint_as_float((unsigned)(v >> 32));
}

// ---------------- mma / ldmatrix / cp.async helpers -------------------------
__device__ __forceinline__ uint32_t smem_to_u32(const void* p) {
    uint32_t a;
    asm("{ .reg .u64 t; cvta.to.shared.u64 t, %1; cvt.u32.u64 %0, t; }" : "=r"(a) : "l"(p));
    return a;
}
#define CP_ASYNC16(dst, src) \
    asm volatile("cp.async.cg.shared.global [%0], [%1], 16;" :: "r"(dst), "l"(src))
#define CP_COMMIT() asm volatile("cp.async.commit_group;" ::: "memory")
#define CP_WAIT(n)  asm volatile("cp.async.wait_group %0;" :: "n"(n) : "memory")

#define LDSM_X4(r0, r1, r2, r3, a) \
    asm volatile("ldmatrix.sync.aligned.m8n8.x4.shared.b16 {%0,%1,%2,%3}, [%4];" \
        : "=r"(r0), "=r"(r1), "=r"(r2), "=r"(r3) : "r"(a))

#define MMA16816(d, a, b0v, b1v) \
    asm volatile("mma.sync.aligned.m16n8k16.row.col.f32.f16.f16.f32 " \
        "{%0,%1,%2,%3}, {%4,%5,%6,%7}, {%8,%9}, {%0,%1,%2,%3};" \
        : "+f"((d)[0]), "+f"((d)[1]), "+f"((d)[2]), "+f"((d)[3]) \
        : "r"((a)[0]), "r"((a)[1]), "r"((a)[2]), "r"((a)[3]), "r"(b0v), "r"(b1v))

// ---------------- device scratch --------------------------------------------
__device__ int d_off[NACT + 1];
__device__ int d_perm[B_SZ];
__device__ float d_gscratch[(size_t)B_SZ * GTOT];
__device__ __half d_Ah[(size_t)B_SZ * GTOT];      // g_next in fp16
__device__ __half d_Wh[(size_t)NSTATES * GTOT];   // W in fp16

// ---------------- fused single-block counting sort --------------------------
__global__ void k_sort(const int* __restrict__ act) {
    __shared__ int cnt[NACT];
    __shared__ int cur[NACT];
    const int t = threadIdx.x;
    const int lane = t & 31;
    if (t < NACT) cnt[t] = 0;
    __syncthreads();
    for (int i = t; i < B_SZ; i += blockDim.x) {
        int a = act[i];
        unsigned mask = __match_any_sync(0xffffffffu, a);
        if (lane == (__ffs(mask) - 1)) atomicAdd(&cnt[a], __popc(mask));
    }
    __syncthreads();
    if (t == 0) {
        int s = 0;
        for (int a = 0; a < NACT; a++) { d_off[a] = s; cur[a] = s; s += cnt[a]; }
        d_off[NACT] = s;
    }
    __syncthreads();
    for (int i = t; i < B_SZ; i += blockDim.x) {
        int a = act[i];
        unsigned mask = __match_any_sync(0xffffffffu, a);
        int leader = __ffs(mask) - 1;
        int rank = __popc(mask & ((1u << lane) - 1u));
        int base = 0;
        if (lane == leader) base = atomicAdd(&cur[a], __popc(mask));
        base = __shfl_sync(0xffffffffu, base, leader);
        d_perm[base + rank] = i;
    }
}

// ---------------- W -> fp16 --------------------------------------------------
__global__ void k_wsplit(const float* __restrict__ W) {
    int i = blockIdx.x * blockDim.x + threadIdx.x;
    float4 w4 = ((const float4*)W)[i];
    ((__half2*)d_Wh)[2 * i]     = __floats2half2_rn(w4.x, w4.y);
    ((__half2*)d_Wh)[2 * i + 1] = __floats2half2_rn(w4.z, w4.w);
}

// ---------------- transition: per-action GEMM + clip + fp16 cast ------------
// Block tile 128 rows x 64 cols, 256 threads, 8x4 microtile, LDS.64 reads.
__global__ void __launch_bounds__(256)
k_transition(const int* __restrict__ csi,
             const float* __restrict__ emb,
             const float* __restrict__ D0, const float* __restrict__ D1,
             const float* __restrict__ D2, const float* __restrict__ D3,
             float* __restrict__ gout)
{
    const int jt = blockIdx.y;
    const int a  = blockIdx.z;
    int jbase, moff, nf; const float* D;
    if (jt < 4)       { jbase = jt * 64;        moff = 0;   nf = 256; D = D0; }
    else if (jt < 8)  { jbase = (jt - 4) * 64;  moff = 256; nf = 256; D = D1; }
    else if (jt < 10) { jbase = (jt - 8) * 64;  moff = 512; nf = 128; D = D2; }
    else              { jbase = (jt - 10) * 64; moff = 640; nf = 128; D = D3; }

    const int row0   = d_off[a] + blockIdx.x * 128;
    const int rowEnd = d_off[a + 1];
    if (row0 >= rowEnd) return;
    const float* __restrict__ Da = D + (size_t)a * nf * nf;

    __shared__ int   permS[128];
    __shared__ int   stateS[128];
    __shared__ float gsm[32][132];
    __shared__ float dsm[32][68];

    const int t = threadIdx.x;
    if (t < 128) {
        int r = row0 + t;
        if (r < rowEnd) { int b = d_perm[r]; permS[t] = b; stateS[t] = csi[b]; }
        else            { permS[t] = -1;     stateS[t] = 0; }
    }
    __syncthreads();

    unsigned long long acc2[8][2];
    #pragma unroll
    for (int i = 0; i < 8; i++) { acc2[i][0] = 0ull; acc2[i][1] = 0ull; }
    const int rs = (t >> 4) * 8;   // 0..120
    const int cs = (t & 15) * 4;   // 0..60

    for (int k0 = 0; k0 < nf; k0 += 32) {
        #pragma unroll
        for (int q = 0; q < 4; q++) {        // gsm: 128 rows x 32 k
            int id = t * 4 + q;              // 0..1023
            int r  = id >> 3;                // 0..127
            int v  = (id & 7) * 4;           // 0..28
            float4 g4 = *(const float4*)(emb + (size_t)stateS[r] * GTOT + moff + k0 + v);
            gsm[v + 0][r] = g4.x; gsm[v + 1][r] = g4.y;
            gsm[v + 2][r] = g4.z; gsm[v + 3][r] = g4.w;
        }
        #pragma unroll
        for (int q = 0; q < 2; q++) {        // dsm: 64 rows x 32 k
            int id = t * 2 + q;              // 0..511
            int r  = id >> 3;                // 0..63
            int v  = (id & 7) * 4;
            float4 dd = *(const float4*)(Da + (size_t)(jbase + r) * nf + k0 + v);
            dsm[v + 0][r] = dd.x; dsm[v + 1][r] = dd.y;
            dsm[v + 2][r] = dd.z; dsm[v + 3][r] = dd.w;
        }
        __syncthreads();
        #pragma unroll
        for (int kk = 0; kk < 32; kk++) {
            const unsigned long long* bp = (const unsigned long long*)&dsm[kk][cs];
            unsigned long long b0 = bp[0], b1 = bp[1];
            const float2* ap = (const float2*)&gsm[kk][rs];
            #pragma unroll
            for (int h = 0; h < 4; h++) {
                float2 av = ap[h];
                unsigned long long a0, a1;
                DUP_F32X2(a0, av.x);
                DUP_F32X2(a1, av.y);
                FMA_F32X2(acc2[2 * h][0],     a0, b0, acc2[2 * h][0]);
                FMA_F32X2(acc2[2 * h][1],     a0, b1, acc2[2 * h][1]);
                FMA_F32X2(acc2[2 * h + 1][0], a1, b0, acc2[2 * h + 1][0]);
                FMA_F32X2(acc2[2 * h + 1][1], a1, b1, acc2[2 * h + 1][1]);
            }
        }
        __syncthreads();
    }

    #pragma unroll
    for (int i = 0; i < 8; i++) {
        int rl = rs + i;
        int borig = permS[rl];
        if (borig < 0) continue;
        int col = moff + jbase + cs;
        float4 g4 = *(const float4*)(emb + (size_t)stateS[rl] * GTOT + col);
        float4 o;
        o.x = fminf(fmaxf(g4.x + f32x2_lo(acc2[i][0]), -1.f), 1.f);
        o.y = fminf(fmaxf(g4.y + f32x2_hi(acc2[i][0]), -1.f), 1.f);
        o.z = fminf(fmaxf(g4.z + f32x2_lo(acc2[i][1]), -1.f), 1.f);
        o.w = fminf(fmaxf(g4.w + f32x2_hi(acc2[i][1]), -1.f), 1.f);
        *(float4*)(gout + (size_t)borig * GTOT + col) = o;

        __half2* dh = (__half2*)(d_Ah + (size_t)borig * GTOT + col);
        dh[0] = __floats2half2_rn(o.x, o.y);
        dh[1] = __floats2half2_rn(o.z, o.w);
    }
}

// ---------------- HMMA logits GEMM ------------------------------------------
// C[b,s] = sum_k A[b,k]*Wh[s,k] + bias[s]      (A, W fp16; f32 accum)
// BM=128, BN=128, BK=64; 8 warps (4M x 2N), warp tile 32x64.
// 3-stage cp.async ring, ONE __syncthreads per K-iter.
#define GEMM_ITERS 12                        // 768 / 64
#define STG_B      32768                     // A 16K + B 16K
#define OFF_B      16384
#define GSM_TOTAL  (3 * STG_B)               // 96 KB

__device__ __forceinline__ void g_load_stage(int it, int stg, int m0, int n0,
                                             int tid, uint32_t smem_base) {
    const int kc   = it * 64;
    const int row  = tid >> 1;               // 0..127
    const int cb   = (tid & 1) * 4;          // chunk base 0 or 4
    const uint32_t sbase = smem_base + stg * STG_B;
    const __half* ah = d_Ah + (size_t)(m0 + row) * GTOT + kc;
    const __half* bw = d_Wh + (size_t)(n0 + row) * GTOT + kc;
    #pragma unroll
    for (int c = 0; c < 4; c++) {
        int ck = cb + c;                                    // 0..7
        uint32_t sw = row * 128 + ((ck ^ (row & 7)) << 4);  // swizzled byte off
        CP_ASYNC16(sbase + sw,           ah + ck * 8);
        CP_ASYNC16(sbase + OFF_B + sw,   bw + ck * 8);
    }
}

__global__ void __launch_bounds__(256, 2)
k_logits(const float* __restrict__ bias, float* __restrict__ out)
{
    extern __shared__ char smem[];
    const uint32_t smem_base = smem_to_u32(smem);
    const int tid  = threadIdx.x;
    const int lane = tid & 31;
    const int wid  = tid >> 5;
    const int wm   = wid >> 1;               // 0..3 -> 32 rows each
    const int wn   = wid & 1;                // 0..1 -> 64 cols each
    const int m0 = blockIdx.y * 128;
    const int n0 = blockIdx.x * 128;

    float acc[2][8][4];
    #pragma unroll
    for (int mt = 0; mt < 2; mt++)
        #pragma unroll
        for (int nt = 0; nt < 8; nt++)
            #pragma unroll
            for (int q = 0; q < 4; q++) acc[mt][nt][q] = 0.f;

    const int lr  = lane & 15;               // row within 16-row tile
    const int lk8 = lane >> 4;               // k8 half (0/1)

    g_load_stage(0, 0, m0, n0, tid, smem_base);
    CP_COMMIT();
    g_load_stage(1, 1, m0, n0, tid, smem_base);
    CP_COMMIT();

    for (int it = 0; it < GEMM_ITERS; it++) {
        CP_WAIT(1);                 // stage it landed (it+1 may be in flight)
        __syncthreads();            // everyone sees stage it; stage it-1 free

        if (it + 2 < GEMM_ITERS) {
            g_load_stage(it + 2, (it + 2) % 3, m0, n0, tid, smem_base);
            CP_COMMIT();
        }

        const uint32_t sbase = smem_base + (it % 3) * STG_B;
        #pragma unroll
        for (int ks = 0; ks < 4; ks++) {
            const int k8 = ks * 2 + lk8;     // 0..7
            uint32_t afr[2][4], bfr[4][4];
            #pragma unroll
            for (int mt = 0; mt < 2; mt++) {
                int row = wm * 32 + mt * 16 + lr;
                uint32_t ad = sbase + row * 128 + ((k8 ^ (row & 7)) << 4);
                LDSM_X4(afr[mt][0], afr[mt][1], afr[mt][2], afr[mt][3], ad);
            }
            #pragma unroll
            for (int np = 0; np < 4; np++) {
                int rn = wn * 64 + np * 16 + lr;
                uint32_t bd = sbase + OFF_B + rn * 128 + ((k8 ^ (rn & 7)) << 4);
                LDSM_X4(bfr[np][0], bfr[np][1], bfr[np][2], bfr[np][3], bd);
            }
            #pragma unroll
            for (int mt = 0; mt < 2; mt++)
                #pragma unroll
                for (int np = 0; np < 4; np++) {
                    MMA16816(acc[mt][2 * np],     afr[mt], bfr[np][0], bfr[np][2]);
                    MMA16816(acc[mt][2 * np + 1], afr[mt], bfr[np][1], bfr[np][3]);
                }
        }
    }

    // epilogue: float2 stores (32B sectors), bias added
    const int cq = 2 * (lane & 3);
    float2 bv[8];
    #pragma unroll
    for (int nt = 0; nt < 8; nt++)
        bv[nt] = *(const float2*)(bias + n0 + wn * 64 + nt * 8 + cq);

    #pragma unroll
    for (int mt = 0; mt < 2; mt++) {
        int rg = m0 + wm * 32 + mt * 16 + (lane >> 2);
        #pragma unroll
        for (int nt = 0; nt < 8; nt++) {
            float* p = out + (size_t)rg * NSTATES + n0 + wn * 64 + nt * 8 + cq;
            float2 v0 = make_float2(acc[mt][nt][0] + bv[nt].x, acc[mt][nt][1] + bv[nt].y);
            float2 v1 = make_float2(acc[mt][nt][2] + bv[nt].x, acc[mt][nt][3] + bv[nt].y);
            *(float2*)p = v0;
            *(float2*)(p + (size_t)8 * NSTATES) = v1;
        }
    }
}

// ---------------- launch -----------------------------------------------------
extern "C" void kernel_launch(void* const* d_in, const int* in_sizes, int n_in,
                              void* d_out, int out_size)
{
    const int *csi, *ai;
    const float *emb, *W, *bias, *D0, *D1, *D2, *D3;
    if (in_sizes[4] == NSTATES) {
        csi = (const int*)d_in[0]; ai = (const int*)d_in[1];
        emb = (const float*)d_in[2]; W = (const float*)d_in[3];
        bias = (const float*)d_in[4];
        D0 = (const float*)d_in[5]; D1 = (const float*)d_in[6];
        D2 = (const float*)d_in[7]; D3 = (const float*)d_in[8];
    } else {
        csi = (const int*)d_in[0]; ai = (const int*)d_in[1];
        emb = (const float*)d_in[2];
        D0 = (const float*)d_in[3]; D1 = (const float*)d_in[4];
        D2 = (const float*)d_in[5]; D3 = (const float*)d_in[6];
        W = (const float*)d_in[7]; bias = (const float*)d_in[8];
    }

    float* out = (float*)d_out;
    float* gout;
    if ((long long)out_size >= (long long)B_SZ * (NSTATES + GTOT)) {
        gout = out + (size_t)B_SZ * NSTATES;
    } else {
        cudaGetSymbolAddress((void**)&gout, d_gscratch);
    }

    k_sort<<<1, 1024>>>(ai);
    k_wsplit<<<(NSTATES * GTOT / 4) / 256, 256>>>(W);

    dim3 tg(128, 12, NACT);
    k_transition<<<tg, 256>>>(csi, emb, D0, D1, D2, D3, gout);

    cudaFuncSetAttribute(k_logits, cudaFuncAttributeMaxDynamicSharedMemorySize, GSM_TOTAL);
    dim3 gg(NSTATES / 128, B_SZ / 128);
    k_logits<<<gg, 256, GSM_TOTAL>>>(bias, out);
}